// round 1
// baseline (speedup 1.0000x reference)
#include <cuda_runtime.h>
#include <math.h>
#include <stdint.h>

#define BB 4
#define SS 4096
#define EE 512
#define HH 8
#define DD 64
#define WW 256
#define BHN (BB*HH)

// Scratch: q/k/v in [b*H+h][s][d] layout (q pre-scaled by 1/sqrt(D))
__device__ float g_q[(size_t)BHN * SS * DD];
__device__ float g_k[(size_t)BHN * SS * DD];
__device__ float g_v[(size_t)BHN * SS * DD];

// ---------------------------------------------------------------------------
// Projection GEMM: C[m,n] = (sum_k X[m,k]*W[n,k] + bias[n]) * scale
// X: [16384, 512] row-major, W: [512, 512] row-major (K contiguous) -> NT gemm.
// Output written permuted into [b*H+h][s][d] with m = b*S+s, n = h*64+d.
// Classic 128x128x8 tile, 256 threads, 8x8 microtile.
// ---------------------------------------------------------------------------
__global__ __launch_bounds__(256, 2)
void proj_kernel(const float* __restrict__ X,
                 const float* __restrict__ Wm,
                 const float* __restrict__ bias,
                 float* __restrict__ Out,
                 float scale)
{
    __shared__ float As[8][128];
    __shared__ float Bs[8][128];

    const int m0 = blockIdx.y * 128;
    const int n0 = blockIdx.x * 128;
    const int tid = threadIdx.x;
    const int ty = tid >> 4;
    const int tx = tid & 15;
    const int lrow = tid >> 1;        // 0..127
    const int kg = (tid & 1) * 4;     // 0 or 4

    const float* Ap = X  + (size_t)(m0 + lrow) * EE + kg;
    const float* Bp = Wm + (size_t)(n0 + lrow) * EE + kg;

    float acc[8][8];
#pragma unroll
    for (int i = 0; i < 8; i++)
#pragma unroll
        for (int j = 0; j < 8; j++) acc[i][j] = 0.f;

    for (int k0 = 0; k0 < EE; k0 += 8) {
        float4 av = *(const float4*)(Ap + k0);
        float4 bv = *(const float4*)(Bp + k0);
        __syncthreads();              // previous compute done before overwrite
        As[kg + 0][lrow] = av.x; As[kg + 1][lrow] = av.y;
        As[kg + 2][lrow] = av.z; As[kg + 3][lrow] = av.w;
        Bs[kg + 0][lrow] = bv.x; Bs[kg + 1][lrow] = bv.y;
        Bs[kg + 2][lrow] = bv.z; Bs[kg + 3][lrow] = bv.w;
        __syncthreads();
#pragma unroll
        for (int kk = 0; kk < 8; kk++) {
            float a[8], b[8];
            *(float4*)(a)     = *(const float4*)(&As[kk][ty * 8]);
            *(float4*)(a + 4) = *(const float4*)(&As[kk][ty * 8 + 4]);
            *(float4*)(b)     = *(const float4*)(&Bs[kk][tx * 8]);
            *(float4*)(b + 4) = *(const float4*)(&Bs[kk][tx * 8 + 4]);
#pragma unroll
            for (int i = 0; i < 8; i++)
#pragma unroll
                for (int j = 0; j < 8; j++)
                    acc[i][j] = fmaf(a[i], b[j], acc[i][j]);
        }
    }

    // Epilogue: bias + scale, write permuted [bh][s][d]
#pragma unroll
    for (int i = 0; i < 8; i++) {
        int m = m0 + ty * 8 + i;
        int b = m >> 12;              // S = 4096
        int s = m & (SS - 1);
#pragma unroll
        for (int j4 = 0; j4 < 8; j4 += 4) {
            int n = n0 + tx * 8 + j4;
            int h = n >> 6;
            int d = n & 63;
            float4 bi = *(const float4*)(bias + n);
            float4 o;
            o.x = (acc[i][j4 + 0] + bi.x) * scale;
            o.y = (acc[i][j4 + 1] + bi.y) * scale;
            o.z = (acc[i][j4 + 2] + bi.z) * scale;
            o.w = (acc[i][j4 + 3] + bi.w) * scale;
            *(float4*)(&Out[((size_t)(b * HH + h) * SS + s) * DD + d]) = o;
        }
    }
}

// ---------------------------------------------------------------------------
// Band attention: per (b,h), query tile of 64 rows, online softmax over
// 9 key chunks of 64 (window j in [i-256, i+256]).  Chunks are always fully
// in-range or fully out-of-range (S, W multiples of 64).  Only chunk 0 needs
// mask jj>=ii, chunk 8 needs jj<=ii.
// Smem: Qt [d][i] (Q^T), KPs [d][j] (K^T) reused as P [i][j], Vs [j][d].
// 3 * 64*64 floats = 48KB static shared exactly.
// ---------------------------------------------------------------------------
__global__ __launch_bounds__(256, 3)
void attn_kernel(float* __restrict__ out)
{
    __shared__ float Qt[64][64];    // [d][i]
    __shared__ float KPs[64][64];   // K as [d][j]; later P as [i][j]
    __shared__ float Vs[64][64];    // [j][d]

    const int bh = blockIdx.y;
    const int bb = bh >> 3;         // H = 8
    const int hh = bh & 7;
    const int i0 = blockIdx.x * 64;
    const int tid = threadIdx.x;
    const int ty = tid >> 4;        // 0..15
    const int tx = tid & 15;        // 0..15

    const float* qg = g_q + (size_t)bh * SS * DD;
    const float* kg = g_k + (size_t)bh * SS * DD;
    const float* vg = g_v + (size_t)bh * SS * DD;

    // Stage Q transposed: Qt[d][i].  i-fast mapping -> conflict-free smem stores.
    {
        int i = tid & 63;
        int db = (tid >> 6) << 2;   // 0,4,8,12
#pragma unroll
        for (int rep = 0; rep < 4; rep++) {
            int d4 = db + rep * 16;
            float4 v = *(const float4*)(qg + (size_t)(i0 + i) * DD + d4);
            Qt[d4 + 0][i] = v.x; Qt[d4 + 1][i] = v.y;
            Qt[d4 + 2][i] = v.z; Qt[d4 + 3][i] = v.w;
        }
    }

    float acc[4][4];
    float mrow[4], lrow[4];
#pragma unroll
    for (int r = 0; r < 4; r++) {
        mrow[r] = -1e30f; lrow[r] = 0.f;
#pragma unroll
        for (int c = 0; c < 4; c++) acc[r][c] = 0.f;
    }

    for (int ch = 0; ch < 9; ch++) {
        int j0 = i0 - WW + ch * 64;
        if (j0 < 0 || j0 >= SS) continue;   // uniform per block

        __syncthreads();   // previous GEMM2 reads of KPs/Vs done

        // Stage K transposed (KPs[d][j]) and V natural (Vs[j][d])
        {
            int j = tid & 63;
            int db = (tid >> 6) << 2;
#pragma unroll
            for (int rep = 0; rep < 4; rep++) {
                int d4 = db + rep * 16;
                float4 kv = *(const float4*)(kg + (size_t)(j0 + j) * DD + d4);
                KPs[d4 + 0][j] = kv.x; KPs[d4 + 1][j] = kv.y;
                KPs[d4 + 2][j] = kv.z; KPs[d4 + 3][j] = kv.w;
            }
            int jr = tid >> 4;              // 0..15
            int dq = (tid & 15) * 4;        // 0..60
#pragma unroll
            for (int rep = 0; rep < 4; rep++) {
                int row = jr + rep * 16;
                float4 vv = *(const float4*)(vg + (size_t)(j0 + row) * DD + dq);
                *(float4*)(&Vs[row][dq]) = vv;
            }
        }
        __syncthreads();

        // GEMM1: s[r][c] = sum_d Qt[d][ty*4+r] * KPs[d][tx*4+c]
        float s[4][4];
#pragma unroll
        for (int r = 0; r < 4; r++)
#pragma unroll
            for (int c = 0; c < 4; c++) s[r][c] = 0.f;
#pragma unroll 16
        for (int d = 0; d < 64; d++) {
            float4 a4 = *(const float4*)(&Qt[d][ty * 4]);
            float4 b4 = *(const float4*)(&KPs[d][tx * 4]);
            float a[4] = {a4.x, a4.y, a4.z, a4.w};
            float b[4] = {b4.x, b4.y, b4.z, b4.w};
#pragma unroll
            for (int r = 0; r < 4; r++)
#pragma unroll
                for (int c = 0; c < 4; c++)
                    s[r][c] = fmaf(a[r], b[c], s[r][c]);
        }

        // Band mask (only first / last chunk are partial)
        if (ch == 0) {
#pragma unroll
            for (int r = 0; r < 4; r++)
#pragma unroll
                for (int c = 0; c < 4; c++)
                    if (tx * 4 + c < ty * 4 + r) s[r][c] = -1e30f;
        } else if (ch == 8) {
#pragma unroll
            for (int r = 0; r < 4; r++)
#pragma unroll
                for (int c = 0; c < 4; c++)
                    if (tx * 4 + c > ty * 4 + r) s[r][c] = -1e30f;
        }

        // Online softmax update (rows ty*4+r owned by the 16 tx lanes; shfl
        // reductions stay within the 16-lane half-warp: lane = (ty&1)*16 + tx)
        float fac[4];
#pragma unroll
        for (int r = 0; r < 4; r++) {
            float vmax = fmaxf(fmaxf(s[r][0], s[r][1]), fmaxf(s[r][2], s[r][3]));
            vmax = fmaxf(vmax, __shfl_xor_sync(0xffffffffu, vmax, 1));
            vmax = fmaxf(vmax, __shfl_xor_sync(0xffffffffu, vmax, 2));
            vmax = fmaxf(vmax, __shfl_xor_sync(0xffffffffu, vmax, 4));
            vmax = fmaxf(vmax, __shfl_xor_sync(0xffffffffu, vmax, 8));
            float mnew = fmaxf(mrow[r], vmax);
            float sum = 0.f;
#pragma unroll
            for (int c = 0; c < 4; c++) {
                s[r][c] = __expf(s[r][c] - mnew);  // masked -> exp(-1e30)=0
                sum += s[r][c];
            }
            sum += __shfl_xor_sync(0xffffffffu, sum, 1);
            sum += __shfl_xor_sync(0xffffffffu, sum, 2);
            sum += __shfl_xor_sync(0xffffffffu, sum, 4);
            sum += __shfl_xor_sync(0xffffffffu, sum, 8);
            fac[r] = __expf(mrow[r] - mnew);
            mrow[r] = mnew;
            lrow[r] = lrow[r] * fac[r] + sum;
#pragma unroll
            for (int c = 0; c < 4; c++) acc[r][c] *= fac[r];
        }

        __syncthreads();   // all GEMM1 reads of KPs done before P overwrite

        // Store P natural layout [i][j] into KPs buffer
#pragma unroll
        for (int r = 0; r < 4; r++) {
            float4 p4 = make_float4(s[r][0], s[r][1], s[r][2], s[r][3]);
            *(float4*)(&KPs[ty * 4 + r][tx * 4]) = p4;
        }
        __syncthreads();

        // GEMM2: acc[r][c] += sum_j P[ty*4+r][j] * Vs[j][tx*4+c]
        // j unrolled by 4 so P fragments load as float4 (j-contiguous).
#pragma unroll 4
        for (int j4 = 0; j4 < 64; j4 += 4) {
            float a[4][4];
#pragma unroll
            for (int r = 0; r < 4; r++)
                *(float4*)(&a[r][0]) = *(const float4*)(&KPs[ty * 4 + r][j4]);
#pragma unroll
            for (int k = 0; k < 4; k++) {
                float4 b4 = *(const float4*)(&Vs[j4 + k][tx * 4]);
#pragma unroll
                for (int r = 0; r < 4; r++) {
                    acc[r][0] = fmaf(a[r][k], b4.x, acc[r][0]);
                    acc[r][1] = fmaf(a[r][k], b4.y, acc[r][1]);
                    acc[r][2] = fmaf(a[r][k], b4.z, acc[r][2]);
                    acc[r][3] = fmaf(a[r][k], b4.w, acc[r][3]);
                }
            }
        }
    }

    // Output: out_flat[s*2048 + b*512 + h*64 + d]  (the (s,b,h,d) reshape)
#pragma unroll
    for (int r = 0; r < 4; r++) {
        int sg = i0 + ty * 4 + r;
        float inv = 1.f / lrow[r];
        float4 o = make_float4(acc[r][0] * inv, acc[r][1] * inv,
                               acc[r][2] * inv, acc[r][3] * inv);
        size_t off = (size_t)sg * 2048 + (size_t)(bb * 512 + hh * 64 + tx * 4);
        *(float4*)(out + off) = o;
    }
}

// ---------------------------------------------------------------------------
// Inputs (metadata order): query, key, value, attention_mask (unused),
// Wq, bq, Wk, bk, Wv, bv.  Output: float32 [B*S*E].
// ---------------------------------------------------------------------------
extern "C" void kernel_launch(void* const* d_in, const int* in_sizes, int n_in,
                              void* d_out, int out_size)
{
    (void)in_sizes; (void)n_in; (void)out_size;
    const float* query = (const float*)d_in[0];
    const float* key   = (const float*)d_in[1];
    const float* value = (const float*)d_in[2];
    const float* Wq = (const float*)d_in[4];
    const float* bq = (const float*)d_in[5];
    const float* Wk = (const float*)d_in[6];
    const float* bk = (const float*)d_in[7];
    const float* Wv = (const float*)d_in[8];
    const float* bv = (const float*)d_in[9];
    float* out = (float*)d_out;

    float *qp, *kp, *vp;
    cudaGetSymbolAddress((void**)&qp, g_q);
    cudaGetSymbolAddress((void**)&kp, g_k);
    cudaGetSymbolAddress((void**)&vp, g_v);

    dim3 gp(EE / 128, (BB * SS) / 128);   // (4, 128)
    proj_kernel<<<gp, 256>>>(query, Wq, bq, qp, 0.125f);  // 1/sqrt(64)
    proj_kernel<<<gp, 256>>>(key,   Wk, bk, kp, 1.0f);
    proj_kernel<<<gp, 256>>>(value, Wv, bv, vp, 1.0f);

    attn_kernel<<<dim3(SS / 64, BHN), 256>>>(out);
}

// round 2
// speedup vs baseline: 1.9799x; 1.9799x over previous
#include <cuda_runtime.h>
#include <math.h>
#include <stdint.h>

#define BB 4
#define SS 4096
#define EE 512
#define HH 8
#define DD 64
#define WW 256
#define BHN (BB*HH)
#define NEG (-1e30f)

// Scratch q/k/v in [b*H+h][s][d] layout (q pre-scaled by 1/sqrt(D))
__device__ float g_q[(size_t)BHN * SS * DD];
__device__ float g_k[(size_t)BHN * SS * DD];
__device__ float g_v[(size_t)BHN * SS * DD];

__device__ __forceinline__ uint32_t f2tf(float f) {
    uint32_t u;
    asm("cvt.rna.tf32.f32 %0, %1;" : "=r"(u) : "f"(f));
    return u;
}

// m16n8k8 tf32 mma, fp32 accumulate. A row-major, B col-major.
__device__ __forceinline__ void mma8(float* c,
                                     uint32_t a0, uint32_t a1, uint32_t a2, uint32_t a3,
                                     uint32_t b0, uint32_t b1) {
    asm volatile(
        "mma.sync.aligned.m16n8k8.row.col.f32.tf32.tf32.f32 "
        "{%0,%1,%2,%3},{%4,%5,%6,%7},{%8,%9},{%0,%1,%2,%3};"
        : "+f"(c[0]), "+f"(c[1]), "+f"(c[2]), "+f"(c[3])
        : "r"(a0), "r"(a1), "r"(a2), "r"(a3), "r"(b0), "r"(b1));
}

// ---------------------------------------------------------------------------
// Projection GEMM (tf32 tensor cores):
// C[m,n] = (sum_k X[m,k]*W[n,k] + bias[n]) * scale, written permuted to
// Out[b*H+h][s][d] with m = b*S+s, n = h*64+d.
// Block tile 128x128, K-chunk 32. 8 warps as 2(m) x 4(n), warp tile 64x32.
// Smem holds operands in fragment-packed layout:
//   Ap[mt][s][lane][4]  -> one LDS.128 per A fragment
//   Bp[nt][s][lane][2]  -> one LDS.64  per B fragment
// ---------------------------------------------------------------------------
__global__ __launch_bounds__(256, 2)
void proj_mma(const float* __restrict__ X,
              const float* __restrict__ Wm,
              const float* __restrict__ bias,
              float* __restrict__ Out,
              float scale)
{
    __shared__ uint32_t Ap[8][4][32][4];   // 16KB
    __shared__ uint32_t Bp[16][4][32][2];  // 16KB

    const int tid = threadIdx.x;
    const int lane = tid & 31;
    const int w = tid >> 5;
    const int wm = w >> 2;     // 0..1
    const int wn = w & 3;      // 0..3
    const int m0 = blockIdx.y * 128;
    const int n0 = blockIdx.x * 128;
    const int g = lane >> 2;
    const int t = lane & 3;

    float acc[4][4][4];
#pragma unroll
    for (int mt = 0; mt < 4; mt++)
#pragma unroll
        for (int nt = 0; nt < 4; nt++)
#pragma unroll
            for (int i = 0; i < 4; i++) acc[mt][nt][i] = 0.f;

    for (int k0 = 0; k0 < EE; k0 += 32) {
        __syncthreads();
        // Stage A (128x32) and B (128x32) into fragment-packed layout.
#pragma unroll
        for (int e = 0; e < 4; e++) {
            int f = tid + 256 * e;          // 0..1023
            int row = f >> 3;               // 0..127
            int cc = f & 7;                 // k-quad: cols 4cc..4cc+3
            int s = cc >> 1;
            // A
            float4 a4 = *(const float4*)(X + (size_t)(m0 + row) * EE + k0 + 4 * cc);
            int mt = row >> 4;
            int rt = row & 15;
            int lb = 4 * (rt & 7);
            int rb = (rt >> 3) + 2 * (cc & 1);
            Ap[mt][s][lb + 0][rb] = f2tf(a4.x);
            Ap[mt][s][lb + 1][rb] = f2tf(a4.y);
            Ap[mt][s][lb + 2][rb] = f2tf(a4.z);
            Ap[mt][s][lb + 3][rb] = f2tf(a4.w);
            // B
            float4 b4 = *(const float4*)(Wm + (size_t)(n0 + row) * EE + k0 + 4 * cc);
            int nt = row >> 3;
            int lbB = 4 * (row & 7);
            int hB = cc & 1;
            Bp[nt][s][lbB + 0][hB] = f2tf(b4.x);
            Bp[nt][s][lbB + 1][hB] = f2tf(b4.y);
            Bp[nt][s][lbB + 2][hB] = f2tf(b4.z);
            Bp[nt][s][lbB + 3][hB] = f2tf(b4.w);
        }
        __syncthreads();

#pragma unroll
        for (int s = 0; s < 4; s++) {
            uint2 bf[4];
#pragma unroll
            for (int nt = 0; nt < 4; nt++)
                bf[nt] = *(const uint2*)&Bp[wn * 4 + nt][s][lane][0];
#pragma unroll
            for (int mt = 0; mt < 4; mt++) {
                uint4 af = *(const uint4*)&Ap[wm * 4 + mt][s][lane][0];
#pragma unroll
                for (int nt = 0; nt < 4; nt++)
                    mma8(acc[mt][nt], af.x, af.y, af.z, af.w, bf[nt].x, bf[nt].y);
            }
        }
    }

    // Epilogue: bias + scale, permuted store.
#pragma unroll
    for (int mt = 0; mt < 4; mt++) {
        int r0 = m0 + wm * 64 + mt * 16 + g;
        int r1 = r0 + 8;
        int b0i = r0 >> 12, s0i = r0 & (SS - 1);
        int b1i = r1 >> 12, s1i = r1 & (SS - 1);
#pragma unroll
        for (int nt = 0; nt < 4; nt++) {
            int n = n0 + wn * 32 + nt * 8 + 2 * t;
            int h = n >> 6, d = n & 63;
            float2 bi = *(const float2*)(bias + n);
            float2 o;
            o.x = (acc[mt][nt][0] + bi.x) * scale;
            o.y = (acc[mt][nt][1] + bi.y) * scale;
            *(float2*)(&Out[((size_t)(b0i * HH + h) * SS + s0i) * DD + d]) = o;
            o.x = (acc[mt][nt][2] + bi.x) * scale;
            o.y = (acc[mt][nt][3] + bi.y) * scale;
            *(float2*)(&Out[((size_t)(b1i * HH + h) * SS + s1i) * DD + d]) = o;
        }
    }
}

// ---------------------------------------------------------------------------
// Band attention (tf32 tensor cores):
// per (b,h): 64-query tile, online softmax over 9 key chunks of 64.
// 128 threads = 4 warps, warp w owns q-rows [16w, 16w+16).
// Q fragments live in 32 registers for the whole block (no smem traffic).
// KP: K fragment-packed, overlaid by P (XOR-swizzled [64][64]) after QK.
// Vb: V fragment-packed.  48KB smem exactly.
// ---------------------------------------------------------------------------
__global__ __launch_bounds__(128)
void attn_mma(float* __restrict__ out)
{
    __shared__ uint32_t KP[8][8][32][2];   // 16KB: K packed, then P overlay
    __shared__ uint32_t Vb[8][8][32][2];   // 16KB: V packed

    const int bh = blockIdx.y;
    const int bb = bh >> 3;
    const int hh = bh & 7;
    const int i0 = blockIdx.x * 64;
    const int tid = threadIdx.x;
    const int w = tid >> 5;
    const int lane = tid & 31;
    const int g = lane >> 2;
    const int t = lane & 3;

    const float* qg = g_q + (size_t)bh * SS * DD;
    const float* kg = g_k + (size_t)bh * SS * DD;
    const float* vg = g_v + (size_t)bh * SS * DD;

    // Build Q fragments once (A-frag layout, tf32), held in registers.
    uint32_t qa[8][4];
    {
        const float* qb = qg + (size_t)(i0 + 16 * w) * DD;
#pragma unroll
        for (int s = 0; s < 8; s++) {
            qa[s][0] = f2tf(qb[g * 64 + 8 * s + t]);
            qa[s][1] = f2tf(qb[(g + 8) * 64 + 8 * s + t]);
            qa[s][2] = f2tf(qb[g * 64 + 8 * s + t + 4]);
            qa[s][3] = f2tf(qb[(g + 8) * 64 + 8 * s + t + 4]);
        }
    }

    float oacc[8][4];
#pragma unroll
    for (int nt = 0; nt < 8; nt++)
#pragma unroll
        for (int i = 0; i < 4; i++) oacc[nt][i] = 0.f;
    float mA = NEG, mB = NEG, lA = 0.f, lB = 0.f;

    const int rA = 16 * w + g;          // first owned row (tile-local)
    const int sw = 4 * g;               // P swizzle key (row & 7 == g)
    uint32_t* Pm = &KP[0][0][0][0];     // P overlay, [64][64]

    for (int ch = 0; ch < 9; ch++) {
        int j0 = i0 - WW + ch * 64;
        if (j0 < 0 || j0 >= SS) continue;   // uniform per block

        __syncthreads();   // prior QK/PV smem reads done before restage

        // Stage K and V fragment-packed (with tf32 conversion).
        const float* kp = kg + (size_t)j0 * DD;
        const float* vp = vg + (size_t)j0 * DD;
#pragma unroll
        for (int e = 0; e < 8; e++) {
            int f = tid + 128 * e;      // 0..1023
            int j = f >> 4;             // 0..63
            int c = f & 15;             // d = 4c..4c+3
            float4 k4 = *(const float4*)(kp + j * 64 + 4 * c);
            int knt = j >> 3, klb = 4 * (j & 7), ks = c >> 1, khf = c & 1;
            KP[knt][ks][klb + 0][khf] = f2tf(k4.x);
            KP[knt][ks][klb + 1][khf] = f2tf(k4.y);
            KP[knt][ks][klb + 2][khf] = f2tf(k4.z);
            KP[knt][ks][klb + 3][khf] = f2tf(k4.w);
            float4 v4 = *(const float4*)(vp + j * 64 + 4 * c);
            int vnt = c >> 1, vs = j >> 3, vhf = (j >> 2) & 1;
            int vl = 16 * (c & 1) + (j & 3);
            Vb[vnt][vs][vl + 0][vhf] = f2tf(v4.x);
            Vb[vnt][vs][vl + 4][vhf] = f2tf(v4.y);
            Vb[vnt][vs][vl + 8][vhf] = f2tf(v4.z);
            Vb[vnt][vs][vl + 12][vhf] = f2tf(v4.w);
        }
        __syncthreads();

        // QK: S = Q @ K^T  (16 rows x 64 cols per warp)
        float sc[8][4];
#pragma unroll
        for (int nt = 0; nt < 8; nt++)
#pragma unroll
            for (int i = 0; i < 4; i++) sc[nt][i] = 0.f;
#pragma unroll
        for (int s = 0; s < 8; s++) {
#pragma unroll
            for (int nt = 0; nt < 8; nt++) {
                uint2 bv = *(const uint2*)&KP[nt][s][lane][0];
                mma8(sc[nt], qa[s][0], qa[s][1], qa[s][2], qa[s][3], bv.x, bv.y);
            }
        }

        // Band mask (chunk 0: need col >= row; chunk 8: col <= row)
        if (ch == 0) {
#pragma unroll
            for (int nt = 0; nt < 8; nt++) {
                int c0 = 8 * nt + 2 * t;
                if (c0     < rA)     sc[nt][0] = NEG;
                if (c0 + 1 < rA)     sc[nt][1] = NEG;
                if (c0     < rA + 8) sc[nt][2] = NEG;
                if (c0 + 1 < rA + 8) sc[nt][3] = NEG;
            }
        } else if (ch == 8) {
#pragma unroll
            for (int nt = 0; nt < 8; nt++) {
                int c0 = 8 * nt + 2 * t;
                if (c0     > rA)     sc[nt][0] = NEG;
                if (c0 + 1 > rA)     sc[nt][1] = NEG;
                if (c0     > rA + 8) sc[nt][2] = NEG;
                if (c0 + 1 > rA + 8) sc[nt][3] = NEG;
            }
        }

        // Online softmax (rows rA and rA+8; reduce across the 4-lane quad)
        float vA = NEG, vB = NEG;
#pragma unroll
        for (int nt = 0; nt < 8; nt++) {
            vA = fmaxf(vA, fmaxf(sc[nt][0], sc[nt][1]));
            vB = fmaxf(vB, fmaxf(sc[nt][2], sc[nt][3]));
        }
        vA = fmaxf(vA, __shfl_xor_sync(0xffffffffu, vA, 1));
        vA = fmaxf(vA, __shfl_xor_sync(0xffffffffu, vA, 2));
        vB = fmaxf(vB, __shfl_xor_sync(0xffffffffu, vB, 1));
        vB = fmaxf(vB, __shfl_xor_sync(0xffffffffu, vB, 2));
        float mAn = fmaxf(mA, vA), mBn = fmaxf(mB, vB);
        float sumA = 0.f, sumB = 0.f;
#pragma unroll
        for (int nt = 0; nt < 8; nt++) {
            sc[nt][0] = __expf(sc[nt][0] - mAn);
            sc[nt][1] = __expf(sc[nt][1] - mAn);
            sc[nt][2] = __expf(sc[nt][2] - mBn);
            sc[nt][3] = __expf(sc[nt][3] - mBn);
            sumA += sc[nt][0] + sc[nt][1];
            sumB += sc[nt][2] + sc[nt][3];
        }
        sumA += __shfl_xor_sync(0xffffffffu, sumA, 1);
        sumA += __shfl_xor_sync(0xffffffffu, sumA, 2);
        sumB += __shfl_xor_sync(0xffffffffu, sumB, 1);
        sumB += __shfl_xor_sync(0xffffffffu, sumB, 2);
        float fA = __expf(mA - mAn), fB = __expf(mB - mBn);
        mA = mAn; mB = mBn;
        lA = lA * fA + sumA;
        lB = lB * fB + sumB;
#pragma unroll
        for (int nt = 0; nt < 8; nt++) {
            oacc[nt][0] *= fA; oacc[nt][1] *= fA;
            oacc[nt][2] *= fB; oacc[nt][3] *= fB;
        }

        __syncthreads();   // all warps done reading K before P overlay

        // Store P (tf32 bits) into XOR-swizzled overlay of KP.
#pragma unroll
        for (int nt = 0; nt < 8; nt++) {
            int colS = (8 * nt + 2 * t) ^ sw;
            uint2 p0 = make_uint2(f2tf(sc[nt][0]), f2tf(sc[nt][1]));
            *(uint2*)&Pm[rA * 64 + colS] = p0;
            uint2 p1 = make_uint2(f2tf(sc[nt][2]), f2tf(sc[nt][3]));
            *(uint2*)&Pm[(rA + 8) * 64 + colS] = p1;
        }
        __syncwarp();      // PV reads only this warp's P rows

        // PV: O += P @ V
#pragma unroll
        for (int s = 0; s < 8; s++) {
            int cA = (8 * s + t) ^ sw;
            int cB = (8 * s + 4 + t) ^ sw;
            uint32_t a0 = Pm[rA * 64 + cA];
            uint32_t a1 = Pm[(rA + 8) * 64 + cA];
            uint32_t a2 = Pm[rA * 64 + cB];
            uint32_t a3 = Pm[(rA + 8) * 64 + cB];
#pragma unroll
            for (int nt = 0; nt < 8; nt++) {
                uint2 bv = *(const uint2*)&Vb[nt][s][lane][0];
                mma8(oacc[nt], a0, a1, a2, a3, bv.x, bv.y);
            }
        }
    }

    // Epilogue: out_flat[s*2048 + b*512 + h*64 + d]
    float iA = 1.f / lA, iB = 1.f / lB;
    size_t baseA = (size_t)(i0 + rA) * 2048 + (size_t)(bb * 512 + hh * 64);
    size_t baseB = baseA + (size_t)8 * 2048;
#pragma unroll
    for (int nt = 0; nt < 8; nt++) {
        int d = 8 * nt + 2 * t;
        float2 o;
        o.x = oacc[nt][0] * iA; o.y = oacc[nt][1] * iA;
        *(float2*)(out + baseA + d) = o;
        o.x = oacc[nt][2] * iB; o.y = oacc[nt][3] * iB;
        *(float2*)(out + baseB + d) = o;
    }
}

// ---------------------------------------------------------------------------
// Inputs (metadata order): query, key, value, attention_mask (unused),
// Wq, bq, Wk, bk, Wv, bv.  Output: float32 [B*S*E].
// ---------------------------------------------------------------------------
extern "C" void kernel_launch(void* const* d_in, const int* in_sizes, int n_in,
                              void* d_out, int out_size)
{
    (void)in_sizes; (void)n_in; (void)out_size;
    const float* query = (const float*)d_in[0];
    const float* key   = (const float*)d_in[1];
    const float* value = (const float*)d_in[2];
    const float* Wq = (const float*)d_in[4];
    const float* bq = (const float*)d_in[5];
    const float* Wk = (const float*)d_in[6];
    const float* bk = (const float*)d_in[7];
    const float* Wv = (const float*)d_in[8];
    const float* bv = (const float*)d_in[9];
    float* out = (float*)d_out;

    float *qp, *kp, *vp;
    cudaGetSymbolAddress((void**)&qp, g_q);
    cudaGetSymbolAddress((void**)&kp, g_k);
    cudaGetSymbolAddress((void**)&vp, g_v);

    dim3 gp(EE / 128, (BB * SS) / 128);   // (4, 128)
    proj_mma<<<gp, 256>>>(query, Wq, bq, qp, 0.125f);  // 1/sqrt(64)
    proj_mma<<<gp, 256>>>(key,   Wk, bk, kp, 1.0f);
    proj_mma<<<gp, 256>>>(value, Wv, bv, vp, 1.0f);

    attn_mma<<<dim3(SS / 64, BHN), 128>>>(out);
}

// round 3
// speedup vs baseline: 1.9820x; 1.0010x over previous
#include <cuda_runtime.h>
#include <math.h>
#include <stdint.h>

#define BB 4
#define SS 4096
#define EE 512
#define HH 8
#define DD 64
#define WW 256
#define BHN (BB*HH)
#define NEG (-1e30f)

// Scratch q/k/v in [b*H+h][s][d] layout (q pre-scaled by 1/sqrt(D))
__device__ float g_q[(size_t)BHN * SS * DD];
__device__ float g_k[(size_t)BHN * SS * DD];
__device__ float g_v[(size_t)BHN * SS * DD];

__device__ __forceinline__ uint32_t f2tf(float f) {
    uint32_t u;
    asm("cvt.rna.tf32.f32 %0, %1;" : "=r"(u) : "f"(f));
    return u;
}

// m16n8k8 tf32 mma, fp32 accumulate. A row-major, B col-major.
__device__ __forceinline__ void mma8(float* c,
                                     uint32_t a0, uint32_t a1, uint32_t a2, uint32_t a3,
                                     uint32_t b0, uint32_t b1) {
    asm volatile(
        "mma.sync.aligned.m16n8k8.row.col.f32.tf32.tf32.f32 "
        "{%0,%1,%2,%3},{%4,%5,%6,%7},{%8,%9},{%0,%1,%2,%3};"
        : "+f"(c[0]), "+f"(c[1]), "+f"(c[2]), "+f"(c[3])
        : "r"(a0), "r"(a1), "r"(a2), "r"(a3), "r"(b0), "r"(b1));
}

// ---------------------------------------------------------------------------
// Projection GEMM (tf32 tensor cores):
// C[m,n] = (sum_k X[m,k]*W[n,k] + bias[n]) * scale, written permuted to
// Out[b*H+h][s][d] with m = b*S+s, n = h*64+d.
// Block tile 128x128, K-chunk 32. 8 warps as 2(m) x 4(n), warp tile 64x32.
// Smem holds operands in fragment-packed layout:
//   Ap[mt][s][lane][4]  -> one LDS.128 per A fragment
//   Bp[nt][s][lane][2]  -> one LDS.64  per B fragment
// ---------------------------------------------------------------------------
__global__ __launch_bounds__(256, 2)
void proj_mma(const float* __restrict__ X,
              const float* __restrict__ Wm,
              const float* __restrict__ bias,
              float* __restrict__ Out,
              float scale)
{
    __shared__ uint32_t Ap[8][4][32][4];   // 16KB
    __shared__ uint32_t Bp[16][4][32][2];  // 16KB

    const int tid = threadIdx.x;
    const int lane = tid & 31;
    const int w = tid >> 5;
    const int wm = w >> 2;     // 0..1
    const int wn = w & 3;      // 0..3
    const int m0 = blockIdx.y * 128;
    const int n0 = blockIdx.x * 128;
    const int g = lane >> 2;
    const int t = lane & 3;

    float acc[4][4][4];
#pragma unroll
    for (int mt = 0; mt < 4; mt++)
#pragma unroll
        for (int nt = 0; nt < 4; nt++)
#pragma unroll
            for (int i = 0; i < 4; i++) acc[mt][nt][i] = 0.f;

    for (int k0 = 0; k0 < EE; k0 += 32) {
        __syncthreads();
        // Stage A (128x32) and B (128x32) into fragment-packed layout.
#pragma unroll
        for (int e = 0; e < 4; e++) {
            int f = tid + 256 * e;          // 0..1023
            int row = f >> 3;               // 0..127
            int cc = f & 7;                 // k-quad: cols 4cc..4cc+3
            int s = cc >> 1;
            // A
            float4 a4 = *(const float4*)(X + (size_t)(m0 + row) * EE + k0 + 4 * cc);
            int mt = row >> 4;
            int rt = row & 15;
            int lb = 4 * (rt & 7);
            int rb = (rt >> 3) + 2 * (cc & 1);
            Ap[mt][s][lb + 0][rb] = f2tf(a4.x);
            Ap[mt][s][lb + 1][rb] = f2tf(a4.y);
            Ap[mt][s][lb + 2][rb] = f2tf(a4.z);
            Ap[mt][s][lb + 3][rb] = f2tf(a4.w);
            // B
            float4 b4 = *(const float4*)(Wm + (size_t)(n0 + row) * EE + k0 + 4 * cc);
            int nt = row >> 3;
            int lbB = 4 * (row & 7);
            int hB = cc & 1;
            Bp[nt][s][lbB + 0][hB] = f2tf(b4.x);
            Bp[nt][s][lbB + 1][hB] = f2tf(b4.y);
            Bp[nt][s][lbB + 2][hB] = f2tf(b4.z);
            Bp[nt][s][lbB + 3][hB] = f2tf(b4.w);
        }
        __syncthreads();

#pragma unroll
        for (int s = 0; s < 4; s++) {
            uint2 bf[4];
#pragma unroll
            for (int nt = 0; nt < 4; nt++)
                bf[nt] = *(const uint2*)&Bp[wn * 4 + nt][s][lane][0];
#pragma unroll
            for (int mt = 0; mt < 4; mt++) {
                uint4 af = *(const uint4*)&Ap[wm * 4 + mt][s][lane][0];
#pragma unroll
                for (int nt = 0; nt < 4; nt++)
                    mma8(acc[mt][nt], af.x, af.y, af.z, af.w, bf[nt].x, bf[nt].y);
            }
        }
    }

    // Epilogue: bias + scale, permuted store.
#pragma unroll
    for (int mt = 0; mt < 4; mt++) {
        int r0 = m0 + wm * 64 + mt * 16 + g;
        int r1 = r0 + 8;
        int b0i = r0 >> 12, s0i = r0 & (SS - 1);
        int b1i = r1 >> 12, s1i = r1 & (SS - 1);
#pragma unroll
        for (int nt = 0; nt < 4; nt++) {
            int n = n0 + wn * 32 + nt * 8 + 2 * t;
            int h = n >> 6, d = n & 63;
            float2 bi = *(const float2*)(bias + n);
            float2 o;
            o.x = (acc[mt][nt][0] + bi.x) * scale;
            o.y = (acc[mt][nt][1] + bi.y) * scale;
            *(float2*)(&Out[((size_t)(b0i * HH + h) * SS + s0i) * DD + d]) = o;
            o.x = (acc[mt][nt][2] + bi.x) * scale;
            o.y = (acc[mt][nt][3] + bi.y) * scale;
            *(float2*)(&Out[((size_t)(b1i * HH + h) * SS + s1i) * DD + d]) = o;
        }
    }
}

// ---------------------------------------------------------------------------
// Band attention (tf32 tensor cores):
// per (b,h): 64-query tile, online softmax over 9 key chunks of 64.
// 128 threads = 4 warps, warp w owns q-rows [16w, 16w+16).
// Q fragments live in 32 registers for the whole block (no smem traffic).
// KP: K fragment-packed, overlaid by P (XOR-swizzled [64][64]) after QK.
// Vb: V fragment-packed.  48KB smem exactly.
// ---------------------------------------------------------------------------
__global__ __launch_bounds__(128)
void attn_mma(float* __restrict__ out)
{
    __shared__ uint32_t KP[8][8][32][2];   // 16KB: K packed, then P overlay
    __shared__ uint32_t Vb[8][8][32][2];   // 16KB: V packed

    const int bh = blockIdx.y;
    const int bb = bh >> 3;
    const int hh = bh & 7;
    const int i0 = blockIdx.x * 64;
    const int tid = threadIdx.x;
    const int w = tid >> 5;
    const int lane = tid & 31;
    const int g = lane >> 2;
    const int t = lane & 3;

    const float* qg = g_q + (size_t)bh * SS * DD;
    const float* kg = g_k + (size_t)bh * SS * DD;
    const float* vg = g_v + (size_t)bh * SS * DD;

    // Build Q fragments once (A-frag layout, tf32), held in registers.
    uint32_t qa[8][4];
    {
        const float* qb = qg + (size_t)(i0 + 16 * w) * DD;
#pragma unroll
        for (int s = 0; s < 8; s++) {
            qa[s][0] = f2tf(qb[g * 64 + 8 * s + t]);
            qa[s][1] = f2tf(qb[(g + 8) * 64 + 8 * s + t]);
            qa[s][2] = f2tf(qb[g * 64 + 8 * s + t + 4]);
            qa[s][3] = f2tf(qb[(g + 8) * 64 + 8 * s + t + 4]);
        }
    }

    float oacc[8][4];
#pragma unroll
    for (int nt = 0; nt < 8; nt++)
#pragma unroll
        for (int i = 0; i < 4; i++) oacc[nt][i] = 0.f;
    float mA = NEG, mB = NEG, lA = 0.f, lB = 0.f;

    const int rA = 16 * w + g;          // first owned row (tile-local)
    const int sw = 4 * g;               // P swizzle key (row & 7 == g)
    uint32_t* Pm = &KP[0][0][0][0];     // P overlay, [64][64]

    for (int ch = 0; ch < 9; ch++) {
        int j0 = i0 - WW + ch * 64;
        if (j0 < 0 || j0 >= SS) continue;   // uniform per block

        __syncthreads();   // prior QK/PV smem reads done before restage

        // Stage K and V fragment-packed (with tf32 conversion).
        const float* kp = kg + (size_t)j0 * DD;
        const float* vp = vg + (size_t)j0 * DD;
#pragma unroll
        for (int e = 0; e < 8; e++) {
            int f = tid + 128 * e;      // 0..1023
            int j = f >> 4;             // 0..63
            int c = f & 15;             // d = 4c..4c+3
            float4 k4 = *(const float4*)(kp + j * 64 + 4 * c);
            int knt = j >> 3, klb = 4 * (j & 7), ks = c >> 1, khf = c & 1;
            KP[knt][ks][klb + 0][khf] = f2tf(k4.x);
            KP[knt][ks][klb + 1][khf] = f2tf(k4.y);
            KP[knt][ks][klb + 2][khf] = f2tf(k4.z);
            KP[knt][ks][klb + 3][khf] = f2tf(k4.w);
            float4 v4 = *(const float4*)(vp + j * 64 + 4 * c);
            int vnt = c >> 1, vs = j >> 3, vhf = (j >> 2) & 1;
            int vl = 16 * (c & 1) + (j & 3);
            Vb[vnt][vs][vl + 0][vhf] = f2tf(v4.x);
            Vb[vnt][vs][vl + 4][vhf] = f2tf(v4.y);
            Vb[vnt][vs][vl + 8][vhf] = f2tf(v4.z);
            Vb[vnt][vs][vl + 12][vhf] = f2tf(v4.w);
        }
        __syncthreads();

        // QK: S = Q @ K^T  (16 rows x 64 cols per warp)
        float sc[8][4];
#pragma unroll
        for (int nt = 0; nt < 8; nt++)
#pragma unroll
            for (int i = 0; i < 4; i++) sc[nt][i] = 0.f;
#pragma unroll
        for (int s = 0; s < 8; s++) {
#pragma unroll
            for (int nt = 0; nt < 8; nt++) {
                uint2 bv = *(const uint2*)&KP[nt][s][lane][0];
                mma8(sc[nt], qa[s][0], qa[s][1], qa[s][2], qa[s][3], bv.x, bv.y);
            }
        }

        // Band mask (chunk 0: need col >= row; chunk 8: col <= row)
        if (ch == 0) {
#pragma unroll
            for (int nt = 0; nt < 8; nt++) {
                int c0 = 8 * nt + 2 * t;
                if (c0     < rA)     sc[nt][0] = NEG;
                if (c0 + 1 < rA)     sc[nt][1] = NEG;
                if (c0     < rA + 8) sc[nt][2] = NEG;
                if (c0 + 1 < rA + 8) sc[nt][3] = NEG;
            }
        } else if (ch == 8) {
#pragma unroll
            for (int nt = 0; nt < 8; nt++) {
                int c0 = 8 * nt + 2 * t;
                if (c0     > rA)     sc[nt][0] = NEG;
                if (c0 + 1 > rA)     sc[nt][1] = NEG;
                if (c0     > rA + 8) sc[nt][2] = NEG;
                if (c0 + 1 > rA + 8) sc[nt][3] = NEG;
            }
        }

        // Online softmax (rows rA and rA+8; reduce across the 4-lane quad)
        float vA = NEG, vB = NEG;
#pragma unroll
        for (int nt = 0; nt < 8; nt++) {
            vA = fmaxf(vA, fmaxf(sc[nt][0], sc[nt][1]));
            vB = fmaxf(vB, fmaxf(sc[nt][2], sc[nt][3]));
        }
        vA = fmaxf(vA, __shfl_xor_sync(0xffffffffu, vA, 1));
        vA = fmaxf(vA, __shfl_xor_sync(0xffffffffu, vA, 2));
        vB = fmaxf(vB, __shfl_xor_sync(0xffffffffu, vB, 1));
        vB = fmaxf(vB, __shfl_xor_sync(0xffffffffu, vB, 2));
        float mAn = fmaxf(mA, vA), mBn = fmaxf(mB, vB);
        float sumA = 0.f, sumB = 0.f;
#pragma unroll
        for (int nt = 0; nt < 8; nt++) {
            sc[nt][0] = __expf(sc[nt][0] - mAn);
            sc[nt][1] = __expf(sc[nt][1] - mAn);
            sc[nt][2] = __expf(sc[nt][2] - mBn);
            sc[nt][3] = __expf(sc[nt][3] - mBn);
            sumA += sc[nt][0] + sc[nt][1];
            sumB += sc[nt][2] + sc[nt][3];
        }
        sumA += __shfl_xor_sync(0xffffffffu, sumA, 1);
        sumA += __shfl_xor_sync(0xffffffffu, sumA, 2);
        sumB += __shfl_xor_sync(0xffffffffu, sumB, 1);
        sumB += __shfl_xor_sync(0xffffffffu, sumB, 2);
        float fA = __expf(mA - mAn), fB = __expf(mB - mBn);
        mA = mAn; mB = mBn;
        lA = lA * fA + sumA;
        lB = lB * fB + sumB;
#pragma unroll
        for (int nt = 0; nt < 8; nt++) {
            oacc[nt][0] *= fA; oacc[nt][1] *= fA;
            oacc[nt][2] *= fB; oacc[nt][3] *= fB;
        }

        __syncthreads();   // all warps done reading K before P overlay

        // Store P (tf32 bits) into XOR-swizzled overlay of KP.
#pragma unroll
        for (int nt = 0; nt < 8; nt++) {
            int colS = (8 * nt + 2 * t) ^ sw;
            uint2 p0 = make_uint2(f2tf(sc[nt][0]), f2tf(sc[nt][1]));
            *(uint2*)&Pm[rA * 64 + colS] = p0;
            uint2 p1 = make_uint2(f2tf(sc[nt][2]), f2tf(sc[nt][3]));
            *(uint2*)&Pm[(rA + 8) * 64 + colS] = p1;
        }
        __syncwarp();      // PV reads only this warp's P rows

        // PV: O += P @ V
#pragma unroll
        for (int s = 0; s < 8; s++) {
            int cA = (8 * s + t) ^ sw;
            int cB = (8 * s + 4 + t) ^ sw;
            uint32_t a0 = Pm[rA * 64 + cA];
            uint32_t a1 = Pm[(rA + 8) * 64 + cA];
            uint32_t a2 = Pm[rA * 64 + cB];
            uint32_t a3 = Pm[(rA + 8) * 64 + cB];
#pragma unroll
            for (int nt = 0; nt < 8; nt++) {
                uint2 bv = *(const uint2*)&Vb[nt][s][lane][0];
                mma8(oacc[nt], a0, a1, a2, a3, bv.x, bv.y);
            }
        }
    }

    // Epilogue: out_flat[s*2048 + b*512 + h*64 + d]
    float iA = 1.f / lA, iB = 1.f / lB;
    size_t baseA = (size_t)(i0 + rA) * 2048 + (size_t)(bb * 512 + hh * 64);
    size_t baseB = baseA + (size_t)8 * 2048;
#pragma unroll
    for (int nt = 0; nt < 8; nt++) {
        int d = 8 * nt + 2 * t;
        float2 o;
        o.x = oacc[nt][0] * iA; o.y = oacc[nt][1] * iA;
        *(float2*)(out + baseA + d) = o;
        o.x = oacc[nt][2] * iB; o.y = oacc[nt][3] * iB;
        *(float2*)(out + baseB + d) = o;
    }
}

// ---------------------------------------------------------------------------
// Inputs (metadata order): query, key, value, attention_mask (unused),
// Wq, bq, Wk, bk, Wv, bv.  Output: float32 [B*S*E].
// ---------------------------------------------------------------------------
extern "C" void kernel_launch(void* const* d_in, const int* in_sizes, int n_in,
                              void* d_out, int out_size)
{
    (void)in_sizes; (void)n_in; (void)out_size;
    const float* query = (const float*)d_in[0];
    const float* key   = (const float*)d_in[1];
    const float* value = (const float*)d_in[2];
    const float* Wq = (const float*)d_in[4];
    const float* bq = (const float*)d_in[5];
    const float* Wk = (const float*)d_in[6];
    const float* bk = (const float*)d_in[7];
    const float* Wv = (const float*)d_in[8];
    const float* bv = (const float*)d_in[9];
    float* out = (float*)d_out;

    float *qp, *kp, *vp;
    cudaGetSymbolAddress((void**)&qp, g_q);
    cudaGetSymbolAddress((void**)&kp, g_k);
    cudaGetSymbolAddress((void**)&vp, g_v);

    dim3 gp(EE / 128, (BB * SS) / 128);   // (4, 128)
    proj_mma<<<gp, 256>>>(query, Wq, bq, qp, 0.125f);  // 1/sqrt(64)
    proj_mma<<<gp, 256>>>(key,   Wk, bk, kp, 1.0f);
    proj_mma<<<gp, 256>>>(value, Wv, bv, vp, 1.0f);

    attn_mma<<<dim3(SS / 64, BHN), 128>>>(out);
}

// round 4
// speedup vs baseline: 2.1286x; 1.0740x over previous
#include <cuda_runtime.h>
#include <math.h>
#include <stdint.h>

#define BB 4
#define SS 4096
#define EE 512
#define HH 8
#define DD 64
#define WW 256
#define BHN (BB*HH)
#define NEG (-1e30f)

// Scratch q/k/v in [b*H+h][s][d] layout (q pre-scaled by 1/sqrt(D))
__device__ float g_q[(size_t)BHN * SS * DD];
__device__ float g_k[(size_t)BHN * SS * DD];
__device__ float g_v[(size_t)BHN * SS * DD];

__device__ __forceinline__ uint32_t f2tf(float f) {
    uint32_t u;
    asm("cvt.rna.tf32.f32 %0, %1;" : "=r"(u) : "f"(f));
    return u;
}

// m16n8k8 tf32 mma, fp32 accumulate. A row-major, B col-major.
__device__ __forceinline__ void mma8(float* c,
                                     uint32_t a0, uint32_t a1, uint32_t a2, uint32_t a3,
                                     uint32_t b0, uint32_t b1) {
    asm volatile(
        "mma.sync.aligned.m16n8k8.row.col.f32.tf32.tf32.f32 "
        "{%0,%1,%2,%3},{%4,%5,%6,%7},{%8,%9},{%0,%1,%2,%3};"
        : "+f"(c[0]), "+f"(c[1]), "+f"(c[2]), "+f"(c[3])
        : "r"(a0), "r"(a1), "r"(a2), "r"(a3), "r"(b0), "r"(b1));
}

// ---------------------------------------------------------------------------
// Projection GEMM (tf32): C[m,n] = (sum_k X[m,k]*W[n,k] + bias[n]) * scale,
// written permuted to Out[b*H+h][s][d] (m = b*S+s, n = h*64+d).
// 128x128 block tile, K-chunk 32, 8 warps (2m x 4n), warp tile 64x32.
// Staging: each warp fills whole fragment slots -> conflict-free STS.128/64.
// ---------------------------------------------------------------------------
__global__ __launch_bounds__(256, 2)
void proj_mma(const float* __restrict__ X,
              const float* __restrict__ Wm,
              const float* __restrict__ bias,
              float* __restrict__ Out,
              float scale)
{
    __shared__ uint32_t Ap[8][4][32][4];   // 16KB: A fragments
    __shared__ uint32_t Bp[16][4][32][2];  // 16KB: B fragments

    const int tid = threadIdx.x;
    const int lane = tid & 31;
    const int w = tid >> 5;
    const int wm = w >> 2;
    const int wn = w & 3;
    const int m0 = blockIdx.y * 128;
    const int n0 = blockIdx.x * 128;
    const int g = lane >> 2;
    const int t = lane & 3;

    float acc[4][4][4];
#pragma unroll
    for (int mt = 0; mt < 4; mt++)
#pragma unroll
        for (int nt = 0; nt < 4; nt++)
#pragma unroll
            for (int i = 0; i < 4; i++) acc[mt][nt][i] = 0.f;

    for (int k0 = 0; k0 < EE; k0 += 32) {
        __syncthreads();
        // A fragments: 32 (mt,s) slots, 4 per warp. Lane writes its own slot:
        // a0=A[r][c], a1=A[r+8][c], a2=A[r][c+4], a3=A[r+8][c+4].
#pragma unroll
        for (int p = 0; p < 4; p++) {
            int pair = w * 4 + p;
            int mt = pair >> 2, s = pair & 3;
            const float* base = X + (size_t)(m0 + mt * 16 + g) * EE + k0 + s * 8 + t;
            uint4 u;
            u.x = f2tf(base[0]);
            u.y = f2tf(base[8 * EE]);
            u.z = f2tf(base[4]);
            u.w = f2tf(base[8 * EE + 4]);
            *(uint4*)&Ap[mt][s][lane][0] = u;
        }
        // B fragments: 64 (nt,s) slots, 8 per warp: b0=B[r][c], b1=B[r][c+4].
#pragma unroll
        for (int p = 0; p < 8; p++) {
            int pair = w * 8 + p;
            int nt = pair >> 2, s = pair & 3;
            const float* base = Wm + (size_t)(n0 + nt * 8 + g) * EE + k0 + s * 8 + t;
            uint2 u;
            u.x = f2tf(base[0]);
            u.y = f2tf(base[4]);
            *(uint2*)&Bp[nt][s][lane][0] = u;
        }
        __syncthreads();

#pragma unroll
        for (int s = 0; s < 4; s++) {
            uint2 bf[4];
#pragma unroll
            for (int nt = 0; nt < 4; nt++)
                bf[nt] = *(const uint2*)&Bp[wn * 4 + nt][s][lane][0];
#pragma unroll
            for (int mt = 0; mt < 4; mt++) {
                uint4 af = *(const uint4*)&Ap[wm * 4 + mt][s][lane][0];
#pragma unroll
                for (int nt = 0; nt < 4; nt++)
                    mma8(acc[mt][nt], af.x, af.y, af.z, af.w, bf[nt].x, bf[nt].y);
            }
        }
    }

    // Epilogue: bias + scale, permuted store.
#pragma unroll
    for (int mt = 0; mt < 4; mt++) {
        int r0 = m0 + wm * 64 + mt * 16 + g;
        int r1 = r0 + 8;
        int b0i = r0 >> 12, s0i = r0 & (SS - 1);
        int b1i = r1 >> 12, s1i = r1 & (SS - 1);
#pragma unroll
        for (int nt = 0; nt < 4; nt++) {
            int n = n0 + wn * 32 + nt * 8 + 2 * t;
            int h = n >> 6, d = n & 63;
            float2 bi = *(const float2*)(bias + n);
            float2 o;
            o.x = (acc[mt][nt][0] + bi.x) * scale;
            o.y = (acc[mt][nt][1] + bi.y) * scale;
            *(float2*)(&Out[((size_t)(b0i * HH + h) * SS + s0i) * DD + d]) = o;
            o.x = (acc[mt][nt][2] + bi.x) * scale;
            o.y = (acc[mt][nt][3] + bi.y) * scale;
            *(float2*)(&Out[((size_t)(b1i * HH + h) * SS + s1i) * DD + d]) = o;
        }
    }
}

// ---------------------------------------------------------------------------
// Band attention (tf32 mma.sync): 64-query tile per (b,h), online softmax
// over 9 key chunks of 64. 4 warps, warp w owns q-rows [16w, 16w+16).
// Q fragments in registers for the whole block. K/V staged as fragment slots
// with conflict-free STS.64 (warp fills whole (nt,s) slots). P overlays KP
// with an XOR swizzle.
// ---------------------------------------------------------------------------
__global__ __launch_bounds__(128)
void attn_mma(float* __restrict__ out)
{
    __shared__ uint32_t KP[8][8][32][2];   // 16KB: K fragments, then P overlay
    __shared__ uint32_t Vb[8][8][32][2];   // 16KB: V fragments

    const int bh = blockIdx.y;
    const int bb = bh >> 3;
    const int hh = bh & 7;
    const int i0 = blockIdx.x * 64;
    const int tid = threadIdx.x;
    const int w = tid >> 5;
    const int lane = tid & 31;
    const int g = lane >> 2;
    const int t = lane & 3;

    const float* qg = g_q + (size_t)bh * SS * DD;
    const float* kg = g_k + (size_t)bh * SS * DD;
    const float* vg = g_v + (size_t)bh * SS * DD;

    // Q fragments (A layout), built once, held in registers.
    uint32_t qa[8][4];
    {
        const float* qb = qg + (size_t)(i0 + 16 * w) * DD;
#pragma unroll
        for (int s = 0; s < 8; s++) {
            qa[s][0] = f2tf(qb[g * 64 + 8 * s + t]);
            qa[s][1] = f2tf(qb[(g + 8) * 64 + 8 * s + t]);
            qa[s][2] = f2tf(qb[g * 64 + 8 * s + t + 4]);
            qa[s][3] = f2tf(qb[(g + 8) * 64 + 8 * s + t + 4]);
        }
    }

    float oacc[8][4];
#pragma unroll
    for (int nt = 0; nt < 8; nt++)
#pragma unroll
        for (int i = 0; i < 4; i++) oacc[nt][i] = 0.f;
    float mA = NEG, mB = NEG, lA = 0.f, lB = 0.f;

    const int rA = 16 * w + g;
    const int sw = 4 * g;
    uint32_t* Pm = &KP[0][0][0][0];

    for (int ch = 0; ch < 9; ch++) {
        int j0 = i0 - WW + ch * 64;
        if (j0 < 0 || j0 >= SS) continue;   // uniform per block

        __syncthreads();   // prior QK/PV smem reads done before restage

        const float* kp = kg + (size_t)j0 * DD;
        const float* vp = vg + (size_t)j0 * DD;
        // K fragments: 64 (nt,s) slots, 16 per warp, conflict-free STS.64.
        // Slot lane value: b0 = K[nt*8+g][s*8+t], b1 = K[..][s*8+t+4].
#pragma unroll
        for (int p = 0; p < 16; p++) {
            int pair = w * 16 + p;
            int nt = pair >> 3, s = pair & 7;
            const float* base = kp + (size_t)(nt * 8 + g) * DD + s * 8 + t;
            uint2 u;
            u.x = f2tf(base[0]);
            u.y = f2tf(base[4]);
            *(uint2*)&KP[nt][s][lane][0] = u;
        }
        // V fragments: b0 = V[s*8+t][nt*8+g], b1 = V[s*8+t+4][nt*8+g].
#pragma unroll
        for (int p = 0; p < 16; p++) {
            int pair = w * 16 + p;
            int nt = pair >> 3, s = pair & 7;
            const float* base = vp + (size_t)(s * 8 + t) * DD + nt * 8 + g;
            uint2 u;
            u.x = f2tf(base[0]);
            u.y = f2tf(base[4 * DD]);
            *(uint2*)&Vb[nt][s][lane][0] = u;
        }
        __syncthreads();

        // QK: S = Q @ K^T (16 rows x 64 cols per warp)
        float sc[8][4];
#pragma unroll
        for (int nt = 0; nt < 8; nt++)
#pragma unroll
            for (int i = 0; i < 4; i++) sc[nt][i] = 0.f;
#pragma unroll
        for (int s = 0; s < 8; s++) {
#pragma unroll
            for (int nt = 0; nt < 8; nt++) {
                uint2 bv = *(const uint2*)&KP[nt][s][lane][0];
                mma8(sc[nt], qa[s][0], qa[s][1], qa[s][2], qa[s][3], bv.x, bv.y);
            }
        }

        // Band mask (chunk 0: col >= row; chunk 8: col <= row)
        if (ch == 0) {
#pragma unroll
            for (int nt = 0; nt < 8; nt++) {
                int c0 = 8 * nt + 2 * t;
                if (c0     < rA)     sc[nt][0] = NEG;
                if (c0 + 1 < rA)     sc[nt][1] = NEG;
                if (c0     < rA + 8) sc[nt][2] = NEG;
                if (c0 + 1 < rA + 8) sc[nt][3] = NEG;
            }
        } else if (ch == 8) {
#pragma unroll
            for (int nt = 0; nt < 8; nt++) {
                int c0 = 8 * nt + 2 * t;
                if (c0     > rA)     sc[nt][0] = NEG;
                if (c0 + 1 > rA)     sc[nt][1] = NEG;
                if (c0     > rA + 8) sc[nt][2] = NEG;
                if (c0 + 1 > rA + 8) sc[nt][3] = NEG;
            }
        }

        // Online softmax (rows rA, rA+8; quad reduction)
        float vA = NEG, vB = NEG;
#pragma unroll
        for (int nt = 0; nt < 8; nt++) {
            vA = fmaxf(vA, fmaxf(sc[nt][0], sc[nt][1]));
            vB = fmaxf(vB, fmaxf(sc[nt][2], sc[nt][3]));
        }
        vA = fmaxf(vA, __shfl_xor_sync(0xffffffffu, vA, 1));
        vA = fmaxf(vA, __shfl_xor_sync(0xffffffffu, vA, 2));
        vB = fmaxf(vB, __shfl_xor_sync(0xffffffffu, vB, 1));
        vB = fmaxf(vB, __shfl_xor_sync(0xffffffffu, vB, 2));
        float mAn = fmaxf(mA, vA), mBn = fmaxf(mB, vB);
        float sumA = 0.f, sumB = 0.f;
#pragma unroll
        for (int nt = 0; nt < 8; nt++) {
            sc[nt][0] = __expf(sc[nt][0] - mAn);
            sc[nt][1] = __expf(sc[nt][1] - mAn);
            sc[nt][2] = __expf(sc[nt][2] - mBn);
            sc[nt][3] = __expf(sc[nt][3] - mBn);
            sumA += sc[nt][0] + sc[nt][1];
            sumB += sc[nt][2] + sc[nt][3];
        }
        sumA += __shfl_xor_sync(0xffffffffu, sumA, 1);
        sumA += __shfl_xor_sync(0xffffffffu, sumA, 2);
        sumB += __shfl_xor_sync(0xffffffffu, sumB, 1);
        sumB += __shfl_xor_sync(0xffffffffu, sumB, 2);
        float fA = __expf(mA - mAn), fB = __expf(mB - mBn);
        mA = mAn; mB = mBn;
        lA = lA * fA + sumA;
        lB = lB * fB + sumB;
#pragma unroll
        for (int nt = 0; nt < 8; nt++) {
            oacc[nt][0] *= fA; oacc[nt][1] *= fA;
            oacc[nt][2] *= fB; oacc[nt][3] *= fB;
        }

        __syncthreads();   // all warps done reading K before P overlay

        // Store P (tf32 bits) into XOR-swizzled overlay of KP.
#pragma unroll
        for (int nt = 0; nt < 8; nt++) {
            int colS = (8 * nt + 2 * t) ^ sw;
            uint2 p0 = make_uint2(f2tf(sc[nt][0]), f2tf(sc[nt][1]));
            *(uint2*)&Pm[rA * 64 + colS] = p0;
            uint2 p1 = make_uint2(f2tf(sc[nt][2]), f2tf(sc[nt][3]));
            *(uint2*)&Pm[(rA + 8) * 64 + colS] = p1;
        }
        __syncwarp();      // PV reads only this warp's P rows

        // PV: O += P @ V
#pragma unroll
        for (int s = 0; s < 8; s++) {
            int cA = (8 * s + t) ^ sw;
            int cB = (8 * s + 4 + t) ^ sw;
            uint32_t a0 = Pm[rA * 64 + cA];
            uint32_t a1 = Pm[(rA + 8) * 64 + cA];
            uint32_t a2 = Pm[rA * 64 + cB];
            uint32_t a3 = Pm[(rA + 8) * 64 + cB];
#pragma unroll
            for (int nt = 0; nt < 8; nt++) {
                uint2 bv = *(const uint2*)&Vb[nt][s][lane][0];
                mma8(oacc[nt], a0, a1, a2, a3, bv.x, bv.y);
            }
        }
    }

    // Epilogue: out_flat[s*2048 + b*512 + h*64 + d]
    float iA = 1.f / lA, iB = 1.f / lB;
    size_t baseA = (size_t)(i0 + rA) * 2048 + (size_t)(bb * 512 + hh * 64);
    size_t baseB = baseA + (size_t)8 * 2048;
#pragma unroll
    for (int nt = 0; nt < 8; nt++) {
        int d = 8 * nt + 2 * t;
        float2 o;
        o.x = oacc[nt][0] * iA; o.y = oacc[nt][1] * iA;
        *(float2*)(out + baseA + d) = o;
        o.x = oacc[nt][2] * iB; o.y = oacc[nt][3] * iB;
        *(float2*)(out + baseB + d) = o;
    }
}

// ---------------------------------------------------------------------------
extern "C" void kernel_launch(void* const* d_in, const int* in_sizes, int n_in,
                              void* d_out, int out_size)
{
    (void)in_sizes; (void)n_in; (void)out_size;
    const float* query = (const float*)d_in[0];
    const float* key   = (const float*)d_in[1];
    const float* value = (const float*)d_in[2];
    const float* Wq = (const float*)d_in[4];
    const float* bq = (const float*)d_in[5];
    const float* Wk = (const float*)d_in[6];
    const float* bk = (const float*)d_in[7];
    const float* Wv = (const float*)d_in[8];
    const float* bv = (const float*)d_in[9];
    float* out = (float*)d_out;

    float *qp, *kp, *vp;
    cudaGetSymbolAddress((void**)&qp, g_q);
    cudaGetSymbolAddress((void**)&kp, g_k);
    cudaGetSymbolAddress((void**)&vp, g_v);

    dim3 gp(EE / 128, (BB * SS) / 128);   // (4, 128)
    proj_mma<<<gp, 256>>>(query, Wq, bq, qp, 0.125f);  // 1/sqrt(64)
    proj_mma<<<gp, 256>>>(key,   Wk, bk, kp, 1.0f);
    proj_mma<<<gp, 256>>>(value, Wv, bv, vp, 1.0f);

    attn_mma<<<dim3(SS / 64, BHN), 128>>>(out);
}